// round 4
// baseline (speedup 1.0000x reference)
#include <cuda_runtime.h>

#define NN 50000
#define NE 800000
#define C 128
#define EK 3
#define LRELU_ALPHA 0.2f
#define SCAN_T 1024

// ---------------- scratch (static device globals; no allocation) ----------
__device__ float g_Wh[(size_t)NN * C];          // 25.6 MB
__device__ float g_s1[NN];
__device__ float g_s2[NN];
__device__ float g_denom[NN * EK];
__device__ float g_workE[(size_t)NE * EK];      // exp(alpha), unshifted
__device__ float g_agg[(size_t)NN * EK * C];    // 76.8 MB (written once)
__device__ int   g_src[NE];
__device__ int   g_dst[NE];
__device__ int   g_cnt[NN];
__device__ int   g_off[NN + 1];
__device__ int   g_pos[NN];
__device__ int   g_csr[NE];
__device__ int   g_is64;

// ---------------- kernels --------------------------------------------------

// Detect whether edge_index buffer is int64 (odd 32-bit words all zero) or int32.
__global__ void detect_kernel(const int* __restrict__ raw) {
    int t = threadIdx.x;                    // 256 threads check words 1,3,...,511
    int nz = (raw[2 * t + 1] != 0) ? 1 : 0;
    int any = __syncthreads_or(nz);
    if (t == 0) g_is64 = any ? 0 : 1;
}

// Unpack edge_index into int32 src/dst arrays regardless of stored dtype.
__global__ void normalize_kernel(const int* __restrict__ raw) {
    int e = blockIdx.x * blockDim.x + threadIdx.x;
    if (e >= NE) return;
    if (g_is64) {               // little-endian low words of int64 values
        g_src[e] = raw[2 * e];
        g_dst[e] = raw[2 * NE + 2 * e];
    } else {
        g_src[e] = raw[e];
        g_dst[e] = raw[NE + e];
    }
}

__global__ void init_kernel() {
    int stride = gridDim.x * blockDim.x;
    int i = blockIdx.x * blockDim.x + threadIdx.x;
    for (int t = i; t < NN * EK; t += stride) g_denom[t] = 0.f;
    for (int t = i; t < NN; t += stride) g_cnt[t] = 0;
}

// C = A[M,K] @ B[K,128], row-major, BM=128, BN=128, BK=16, TM=TN=8, 256 thr
// AGG=false: A = Aext (h),    out = g_Wh,  K=128
// AGG=true : A = g_agg,       out = Cext,  K=384
template <bool AGG>
__global__ __launch_bounds__(256) void sgemm128(
    const float* __restrict__ Aext, const float* __restrict__ B,
    float* __restrict__ Cext, int M, int K)
{
    const int BM = 128, BN = 128, BK = 16, TM = 8, TN = 8;
    const float* A  = AGG ? (const float*)g_agg : Aext;
    float*       Cm = AGG ? Cext : (float*)g_Wh;

    __shared__ float As[BK][BM];
    __shared__ float Bs[BK][BN];
    int tid = threadIdx.x;
    int tr = tid / 16, tc = tid % 16;
    int row0 = blockIdx.x * BM;

    float acc[TM][TN];
#pragma unroll
    for (int i = 0; i < TM; i++)
#pragma unroll
        for (int j = 0; j < TN; j++) acc[i][j] = 0.f;

    int arow = tid >> 2;       // 0..63
    int acol4 = tid & 3;       // 0..3
    int brow = tid >> 5;       // 0..7
    int bcol4 = tid & 31;      // 0..31

    for (int kt = 0; kt < K; kt += BK) {
#pragma unroll
        for (int p = 0; p < 2; ++p) {
            int r = arow + p * 64;
            int gr = row0 + r;
            float4 v = make_float4(0.f, 0.f, 0.f, 0.f);
            if (gr < M)
                v = *reinterpret_cast<const float4*>(A + (size_t)gr * K + kt + acol4 * 4);
            As[acol4 * 4 + 0][r] = v.x;
            As[acol4 * 4 + 1][r] = v.y;
            As[acol4 * 4 + 2][r] = v.z;
            As[acol4 * 4 + 3][r] = v.w;
        }
#pragma unroll
        for (int p = 0; p < 2; ++p) {
            int kb = brow + p * 8;
            float4 v = *reinterpret_cast<const float4*>(B + (size_t)(kt + kb) * BN + bcol4 * 4);
            *reinterpret_cast<float4*>(&Bs[kb][bcol4 * 4]) = v;
        }
        __syncthreads();
#pragma unroll
        for (int kk = 0; kk < BK; ++kk) {
            float ra[TM], rb[TN];
#pragma unroll
            for (int i = 0; i < TM; i++) ra[i] = As[kk][tr * TM + i];
#pragma unroll
            for (int j = 0; j < TN; j++) rb[j] = Bs[kk][tc * TN + j];
#pragma unroll
            for (int i = 0; i < TM; i++)
#pragma unroll
                for (int j = 0; j < TN; j++) acc[i][j] += ra[i] * rb[j];
        }
        __syncthreads();
    }
#pragma unroll
    for (int i = 0; i < TM; i++) {
        int gr = row0 + tr * TM + i;
        if (gr < M) {
#pragma unroll
            for (int j = 0; j < TN; j += 4) {
                float4 v = make_float4(acc[i][j], acc[i][j + 1], acc[i][j + 2], acc[i][j + 3]);
                *reinterpret_cast<float4*>(Cm + (size_t)gr * BN + tc * TN + j) = v;
            }
        }
    }
}

// s1 = Wh@a1, s2 = Wh@a2; one warp per node
__global__ void scores_kernel(const float* __restrict__ a1, const float* __restrict__ a2) {
    int gw = (blockIdx.x * blockDim.x + threadIdx.x) >> 5;
    int lane = threadIdx.x & 31;
    if (gw >= NN) return;
    float4 w  = reinterpret_cast<const float4*>(g_Wh + (size_t)gw * C)[lane];
    float4 v1 = reinterpret_cast<const float4*>(a1)[lane];
    float4 v2 = reinterpret_cast<const float4*>(a2)[lane];
    float d1 = w.x * v1.x + w.y * v1.y + w.z * v1.z + w.w * v1.w;
    float d2 = w.x * v2.x + w.y * v2.y + w.z * v2.z + w.w * v2.w;
#pragma unroll
    for (int o = 16; o; o >>= 1) {
        d1 += __shfl_xor_sync(0xffffffffu, d1, o);
        d2 += __shfl_xor_sync(0xffffffffu, d2, o);
    }
    if (lane == 0) { g_s1[gw] = d1; g_s2[gw] = d2; }
}

// edge pass A: ex = exp(leakyrelu(s1[src]+s2[dst]) * ef); denom += ex; degree count
// (softmax is shift-invariant, so the segment-max subtraction is dropped)
__global__ void edge_prep_kernel(const float* __restrict__ ef) {
    int e = blockIdx.x * blockDim.x + threadIdx.x;
    if (e >= NE) return;
    int src = g_src[e];
    int dst = g_dst[e];
    float v = g_s1[src] + g_s2[dst];
    v = (v >= 0.f) ? v : LRELU_ALPHA * v;
#pragma unroll
    for (int k = 0; k < EK; k++) {
        float ex = __expf(v * ef[e * EK + k]) ;
        g_workE[(size_t)e * EK + k] = ex;
        atomicAdd(&g_denom[dst * EK + k], ex);
    }
    atomicAdd(&g_cnt[dst], 1);
}

// single-block exclusive scan of g_cnt -> g_off / g_pos
__global__ __launch_bounds__(SCAN_T) void scan_kernel() {
    __shared__ int s[SCAN_T];
    const int PER = (NN + SCAN_T - 1) / SCAN_T;
    int tid = threadIdx.x;
    int base = tid * PER;
    int sum = 0;
    for (int j = 0; j < PER; j++) {
        int idx = base + j;
        if (idx < NN) sum += g_cnt[idx];
    }
    s[tid] = sum;
    __syncthreads();
    for (int off = 1; off < SCAN_T; off <<= 1) {
        int v = (tid >= off) ? s[tid - off] : 0;
        __syncthreads();
        s[tid] += v;
        __syncthreads();
    }
    int run = s[tid] - sum;   // exclusive prefix for this chunk
    for (int j = 0; j < PER; j++) {
        int idx = base + j;
        if (idx < NN) {
            g_off[idx] = run;
            g_pos[idx] = run;
            run += g_cnt[idx];
        }
    }
    if (tid == SCAN_T - 1) g_off[NN] = s[SCAN_T - 1];
}

// edge pass B: bin edge ids into CSR order by dst
__global__ void edge_bin_kernel() {
    int e = blockIdx.x * blockDim.x + threadIdx.x;
    if (e >= NE) return;
    int p = atomicAdd(&g_pos[g_dst[e]], 1);
    g_csr[p] = e;
}

// gather: one warp per node; agg[n,k,:] = (1/denom_k) * sum_e ex_k * Wh[src_e]
__global__ void aggregate_kernel() {
    int gw = (blockIdx.x * blockDim.x + threadIdx.x) >> 5;
    int lane = threadIdx.x & 31;
    if (gw >= NN) return;
    int beg = g_off[gw], end = g_off[gw + 1];

    float inv0 = 1.f / (g_denom[gw * EK + 0] + 1e-16f);
    float inv1 = 1.f / (g_denom[gw * EK + 1] + 1e-16f);
    float inv2 = 1.f / (g_denom[gw * EK + 2] + 1e-16f);

    float4 acc0 = make_float4(0.f, 0.f, 0.f, 0.f);
    float4 acc1 = acc0, acc2 = acc0;

    for (int t = beg; t < end; ++t) {
        int e   = g_csr[t];
        int src = g_src[e];
        float ex0 = g_workE[(size_t)e * EK + 0];
        float ex1 = g_workE[(size_t)e * EK + 1];
        float ex2 = g_workE[(size_t)e * EK + 2];
        float4 w = reinterpret_cast<const float4*>(g_Wh + (size_t)src * C)[lane];
        acc0.x += w.x * ex0; acc0.y += w.y * ex0; acc0.z += w.z * ex0; acc0.w += w.w * ex0;
        acc1.x += w.x * ex1; acc1.y += w.y * ex1; acc1.z += w.z * ex1; acc1.w += w.w * ex1;
        acc2.x += w.x * ex2; acc2.y += w.y * ex2; acc2.z += w.z * ex2; acc2.w += w.w * ex2;
    }
    acc0.x *= inv0; acc0.y *= inv0; acc0.z *= inv0; acc0.w *= inv0;
    acc1.x *= inv1; acc1.y *= inv1; acc1.z *= inv1; acc1.w *= inv1;
    acc2.x *= inv2; acc2.y *= inv2; acc2.z *= inv2; acc2.w *= inv2;

    float* base = g_agg + (size_t)gw * (EK * C);
    reinterpret_cast<float4*>(base)[lane]         = acc0;
    reinterpret_cast<float4*>(base + C)[lane]     = acc1;
    reinterpret_cast<float4*>(base + 2 * C)[lane] = acc2;
}

// ---------------- launch ----------------------------------------------------

extern "C" void kernel_launch(void* const* d_in, const int* in_sizes, int n_in,
                              void* d_out, int out_size) {
    const float* h    = (const float*)d_in[0];
    const int*   eraw = (const int*)d_in[1];
    const float* ef   = (const float*)d_in[2];
    const float* W    = (const float*)d_in[3];
    const float* a1   = (const float*)d_in[4];
    const float* a2   = (const float*)d_in[5];
    const float* Wout = (const float*)d_in[6];
    float*       out  = (float*)d_out;

    const int MBLK = (NN + 127) / 128;

    detect_kernel<<<1, 256>>>(eraw);
    normalize_kernel<<<(NE + 255) / 256, 256>>>(eraw);
    init_kernel<<<512, 256>>>();
    sgemm128<false><<<MBLK, 256>>>(h, W, nullptr, NN, C);
    scores_kernel<<<(NN * 32 + 255) / 256, 256>>>(a1, a2);
    edge_prep_kernel<<<(NE + 255) / 256, 256>>>(ef);
    scan_kernel<<<1, SCAN_T>>>();
    edge_bin_kernel<<<(NE + 255) / 256, 256>>>();
    aggregate_kernel<<<(NN * 32 + 255) / 256, 256>>>();
    sgemm128<true><<<MBLK, 256>>>(nullptr, Wout, out, NN, EK * C);
}

// round 5
// speedup vs baseline: 1.0015x; 1.0015x over previous
#include <cuda_runtime.h>
#include <cstdint>

#define NN 50000
#define NE 800000
#define C 128
#define EK 3
#define LRELU_ALPHA 0.2f
#define SCAN_T 1024
#define SPAD 136   // smem row stride (floats): conflict-free & 16B aligned

// ---------------- scratch (static device globals; no allocation) ----------
__device__ float g_Wh[(size_t)NN * C];          // 25.6 MB
__device__ float g_s1[NN];
__device__ float g_s2[NN];
__device__ float g_denom[NN * EK];
__device__ float g_workE[(size_t)NE * EK];      // exp(alpha), unshifted
__device__ float g_agg[(size_t)NN * EK * C];    // 76.8 MB (written once)
__device__ int   g_src[NE];
__device__ int   g_dst[NE];
__device__ int   g_cnt[NN];
__device__ int   g_off[NN + 1];
__device__ int   g_pos[NN];
__device__ int   g_csr[NE];
__device__ int   g_is64;

// ---------------- kernels --------------------------------------------------

// Detect whether edge_index buffer is int64 (odd 32-bit words all zero) or int32.
__global__ void detect_kernel(const int* __restrict__ raw) {
    int t = threadIdx.x;                    // 256 threads check words 1,3,...,511
    int nz = (raw[2 * t + 1] != 0) ? 1 : 0;
    int any = __syncthreads_or(nz);
    if (t == 0) g_is64 = any ? 0 : 1;
}

// Unpack edge_index into int32 src/dst arrays; also zero denom/cnt (init fused).
__global__ void normalize_kernel(const int* __restrict__ raw) {
    int e = blockIdx.x * blockDim.x + threadIdx.x;
    if (e >= NE) return;
    if (g_is64) {               // little-endian low words of int64 values
        g_src[e] = raw[2 * e];
        g_dst[e] = raw[2 * NE + 2 * e];
    } else {
        g_src[e] = raw[e];
        g_dst[e] = raw[NE + e];
    }
    if (e < NN * EK) g_denom[e] = 0.f;
    if (e < NN)      g_cnt[e]  = 0;
}

// -------- tf32 tensor-core GEMM with exact 2-term split (3xTF32) ----------
// C = A[M,K] @ B[K,128]; AGG=false: A=h ext, out=g_Wh; AGG=true: A=g_agg, out=ext
#define MMA_TF32(c, a, b0, b1)                                                 \
    asm volatile(                                                              \
        "mma.sync.aligned.m16n8k8.row.col.f32.tf32.tf32.f32 "                  \
        "{%0,%1,%2,%3}, {%4,%5,%6,%7}, {%8,%9}, {%0,%1,%2,%3};"                \
        : "+f"(c[0]), "+f"(c[1]), "+f"(c[2]), "+f"(c[3])                       \
        : "r"(a[0]), "r"(a[1]), "r"(a[2]), "r"(a[3]), "r"(b0), "r"(b1))

template <bool AGG>
__global__ __launch_bounds__(256) void tf32gemm(
    const float* __restrict__ Aext, const float* __restrict__ B,
    float* __restrict__ Cext, int M, int K)
{
    const int BM = 128, BN = 128, BK = 16;
    const float* A  = AGG ? (const float*)g_agg : Aext;
    float*       Cm = AGG ? Cext : (float*)g_Wh;

    __shared__ float Ahi[BK][SPAD], Alo[BK][SPAD];
    __shared__ float Bhi[BK][SPAD], Blo[BK][SPAD];

    int tid  = threadIdx.x;
    int lane = tid & 31;
    int wid  = tid >> 5;
    int gid  = lane >> 2;      // group id 0..7
    int tig  = lane & 3;       // thread-in-group 0..3
    int warp_m = wid & 3;      // 4 warps along M (32 rows each)
    int warp_n = wid >> 2;     // 2 warps along N (64 cols each)
    int row0 = blockIdx.x * BM;

    float acc[2][8][4] = {};

    int arow  = tid >> 2;      // 0..63
    int acol4 = tid & 3;       // 0..3
    int brow  = tid >> 5;      // 0..7
    int bcol4 = tid & 31;      // 0..31

    for (int kt = 0; kt < K; kt += BK) {
#pragma unroll
        for (int p = 0; p < 2; ++p) {
            int r = arow + p * 64;
            int gr = row0 + r;
            float4 v = make_float4(0.f, 0.f, 0.f, 0.f);
            if (gr < M)
                v = *reinterpret_cast<const float4*>(A + (size_t)gr * K + kt + acol4 * 4);
            float vv[4] = {v.x, v.y, v.z, v.w};
#pragma unroll
            for (int j = 0; j < 4; ++j) {
                float hi = __uint_as_float(__float_as_uint(vv[j]) & 0xFFFFE000u);
                Ahi[acol4 * 4 + j][r] = hi;
                Alo[acol4 * 4 + j][r] = vv[j] - hi;
            }
        }
#pragma unroll
        for (int p = 0; p < 2; ++p) {
            int kb = brow + p * 8;
            float4 v = *reinterpret_cast<const float4*>(B + (size_t)(kt + kb) * BN + bcol4 * 4);
            float vv[4] = {v.x, v.y, v.z, v.w};
#pragma unroll
            for (int j = 0; j < 4; ++j) {
                float hi = __uint_as_float(__float_as_uint(vv[j]) & 0xFFFFE000u);
                Bhi[kb][bcol4 * 4 + j] = hi;
                Blo[kb][bcol4 * 4 + j] = vv[j] - hi;
            }
        }
        __syncthreads();

#pragma unroll
        for (int s = 0; s < 2; ++s) {
            int k0 = s * 8;
            unsigned ah[2][4], al[2][4];
#pragma unroll
            for (int mt = 0; mt < 2; ++mt) {
                int rb = warp_m * 32 + mt * 16;
                ah[mt][0] = __float_as_uint(Ahi[k0 + tig    ][rb + gid    ]);
                ah[mt][1] = __float_as_uint(Ahi[k0 + tig    ][rb + gid + 8]);
                ah[mt][2] = __float_as_uint(Ahi[k0 + tig + 4][rb + gid    ]);
                ah[mt][3] = __float_as_uint(Ahi[k0 + tig + 4][rb + gid + 8]);
                al[mt][0] = __float_as_uint(Alo[k0 + tig    ][rb + gid    ]);
                al[mt][1] = __float_as_uint(Alo[k0 + tig    ][rb + gid + 8]);
                al[mt][2] = __float_as_uint(Alo[k0 + tig + 4][rb + gid    ]);
                al[mt][3] = __float_as_uint(Alo[k0 + tig + 4][rb + gid + 8]);
            }
#pragma unroll
            for (int nt = 0; nt < 8; ++nt) {
                int cb = warp_n * 64 + nt * 8;
                unsigned bh0 = __float_as_uint(Bhi[k0 + tig    ][cb + gid]);
                unsigned bh1 = __float_as_uint(Bhi[k0 + tig + 4][cb + gid]);
                unsigned bl0 = __float_as_uint(Blo[k0 + tig    ][cb + gid]);
                unsigned bl1 = __float_as_uint(Blo[k0 + tig + 4][cb + gid]);
#pragma unroll
                for (int mt = 0; mt < 2; ++mt) {
                    MMA_TF32(acc[mt][nt], ah[mt], bh0, bh1);
                    MMA_TF32(acc[mt][nt], ah[mt], bl0, bl1);
                    MMA_TF32(acc[mt][nt], al[mt], bh0, bh1);
                }
            }
        }
        __syncthreads();
    }

#pragma unroll
    for (int mt = 0; mt < 2; ++mt) {
#pragma unroll
        for (int nt = 0; nt < 8; ++nt) {
            int r1 = row0 + warp_m * 32 + mt * 16 + gid;
            int r2 = r1 + 8;
            int cc = warp_n * 64 + nt * 8 + tig * 2;
            if (r1 < M)
                *reinterpret_cast<float2*>(Cm + (size_t)r1 * BN + cc) =
                    make_float2(acc[mt][nt][0], acc[mt][nt][1]);
            if (r2 < M)
                *reinterpret_cast<float2*>(Cm + (size_t)r2 * BN + cc) =
                    make_float2(acc[mt][nt][2], acc[mt][nt][3]);
        }
    }
}

// s1 = Wh@a1, s2 = Wh@a2; one warp per node
__global__ void scores_kernel(const float* __restrict__ a1, const float* __restrict__ a2) {
    int gw = (blockIdx.x * blockDim.x + threadIdx.x) >> 5;
    int lane = threadIdx.x & 31;
    if (gw >= NN) return;
    float4 w  = reinterpret_cast<const float4*>(g_Wh + (size_t)gw * C)[lane];
    float4 v1 = reinterpret_cast<const float4*>(a1)[lane];
    float4 v2 = reinterpret_cast<const float4*>(a2)[lane];
    float d1 = w.x * v1.x + w.y * v1.y + w.z * v1.z + w.w * v1.w;
    float d2 = w.x * v2.x + w.y * v2.y + w.z * v2.z + w.w * v2.w;
#pragma unroll
    for (int o = 16; o; o >>= 1) {
        d1 += __shfl_xor_sync(0xffffffffu, d1, o);
        d2 += __shfl_xor_sync(0xffffffffu, d2, o);
    }
    if (lane == 0) { g_s1[gw] = d1; g_s2[gw] = d2; }
}

// edge pass A: ex = exp(leakyrelu(s1[src]+s2[dst]) * ef); denom += ex; degree count
__global__ void edge_prep_kernel(const float* __restrict__ ef) {
    int e = blockIdx.x * blockDim.x + threadIdx.x;
    if (e >= NE) return;
    int src = g_src[e];
    int dst = g_dst[e];
    float v = g_s1[src] + g_s2[dst];
    v = (v >= 0.f) ? v : LRELU_ALPHA * v;
#pragma unroll
    for (int k = 0; k < EK; k++) {
        float ex = __expf(v * ef[e * EK + k]);
        g_workE[(size_t)e * EK + k] = ex;
        atomicAdd(&g_denom[dst * EK + k], ex);
    }
    atomicAdd(&g_cnt[dst], 1);
}

// single-block exclusive scan of g_cnt -> g_off / g_pos
__global__ __launch_bounds__(SCAN_T) void scan_kernel() {
    __shared__ int s[SCAN_T];
    const int PER = (NN + SCAN_T - 1) / SCAN_T;
    int tid = threadIdx.x;
    int base = tid * PER;
    int sum = 0;
    for (int j = 0; j < PER; j++) {
        int idx = base + j;
        if (idx < NN) sum += g_cnt[idx];
    }
    s[tid] = sum;
    __syncthreads();
    for (int off = 1; off < SCAN_T; off <<= 1) {
        int v = (tid >= off) ? s[tid - off] : 0;
        __syncthreads();
        s[tid] += v;
        __syncthreads();
    }
    int run = s[tid] - sum;   // exclusive prefix for this chunk
    for (int j = 0; j < PER; j++) {
        int idx = base + j;
        if (idx < NN) {
            g_off[idx] = run;
            g_pos[idx] = run;
            run += g_cnt[idx];
        }
    }
    if (tid == SCAN_T - 1) g_off[NN] = s[SCAN_T - 1];
}

// edge pass B: bin edge ids into CSR order by dst
__global__ void edge_bin_kernel() {
    int e = blockIdx.x * blockDim.x + threadIdx.x;
    if (e >= NE) return;
    int p = atomicAdd(&g_pos[g_dst[e]], 1);
    g_csr[p] = e;
}

// gather: one warp per node; agg[n,k,:] = (1/denom_k) * sum_e ex_k * Wh[src_e]
__global__ void aggregate_kernel() {
    int gw = (blockIdx.x * blockDim.x + threadIdx.x) >> 5;
    int lane = threadIdx.x & 31;
    if (gw >= NN) return;
    int beg = g_off[gw], end = g_off[gw + 1];

    float inv0 = 1.f / (g_denom[gw * EK + 0] + 1e-16f);
    float inv1 = 1.f / (g_denom[gw * EK + 1] + 1e-16f);
    float inv2 = 1.f / (g_denom[gw * EK + 2] + 1e-16f);

    float4 acc0 = make_float4(0.f, 0.f, 0.f, 0.f);
    float4 acc1 = acc0, acc2 = acc0;

    for (int t = beg; t < end; ++t) {
        int e   = g_csr[t];
        int src = g_src[e];
        float ex0 = g_workE[(size_t)e * EK + 0];
        float ex1 = g_workE[(size_t)e * EK + 1];
        float ex2 = g_workE[(size_t)e * EK + 2];
        float4 w = reinterpret_cast<const float4*>(g_Wh + (size_t)src * C)[lane];
        acc0.x += w.x * ex0; acc0.y += w.y * ex0; acc0.z += w.z * ex0; acc0.w += w.w * ex0;
        acc1.x += w.x * ex1; acc1.y += w.y * ex1; acc1.z += w.z * ex1; acc1.w += w.w * ex1;
        acc2.x += w.x * ex2; acc2.y += w.y * ex2; acc2.z += w.z * ex2; acc2.w += w.w * ex2;
    }
    acc0.x *= inv0; acc0.y *= inv0; acc0.z *= inv0; acc0.w *= inv0;
    acc1.x *= inv1; acc1.y *= inv1; acc1.z *= inv1; acc1.w *= inv1;
    acc2.x *= inv2; acc2.y *= inv2; acc2.z *= inv2; acc2.w *= inv2;

    float* base = g_agg + (size_t)gw * (EK * C);
    reinterpret_cast<float4*>(base)[lane]         = acc0;
    reinterpret_cast<float4*>(base + C)[lane]     = acc1;
    reinterpret_cast<float4*>(base + 2 * C)[lane] = acc2;
}

// ---------------- launch ----------------------------------------------------

extern "C" void kernel_launch(void* const* d_in, const int* in_sizes, int n_in,
                              void* d_out, int out_size) {
    const float* h    = (const float*)d_in[0];
    const int*   eraw = (const int*)d_in[1];
    const float* ef   = (const float*)d_in[2];
    const float* W    = (const float*)d_in[3];
    const float* a1   = (const float*)d_in[4];
    const float* a2   = (const float*)d_in[5];
    const float* Wout = (const float*)d_in[6];
    float*       out  = (float*)d_out;

    const int MBLK = (NN + 127) / 128;

    detect_kernel<<<1, 256>>>(eraw);
    normalize_kernel<<<(NE + 255) / 256, 256>>>(eraw);
    tf32gemm<false><<<MBLK, 256>>>(h, W, nullptr, NN, C);
    scores_kernel<<<(NN * 32 + 255) / 256, 256>>>(a1, a2);
    edge_prep_kernel<<<(NE + 255) / 256, 256>>>(ef);
    scan_kernel<<<1, SCAN_T>>>();
    edge_bin_kernel<<<(NE + 255) / 256, 256>>>();
    aggregate_kernel<<<(NN * 32 + 255) / 256, 256>>>();
    tf32gemm<true><<<MBLK, 256>>>(nullptr, Wout, out, NN, EK * C);
}

// round 7
// speedup vs baseline: 1.3674x; 1.3653x over previous
#include <cuda_runtime.h>
#include <cuda_bf16.h>
#include <cstdint>

#define NN 50000
#define NE 800000
#define C 128
#define EK 3
#define LRELU_ALPHA 0.2f
#define SCAN_T 1024
#define RSTRIDE 80          // smem row stride in bytes (bank-conflict-free, 16B-aligned)
#define STAGE_BYTES 40960   // Ah(10240) Al(10240) Bh(10240) Bl(10240)

// ---------------- scratch ----------------------------------------------------
__device__ float g_Wh[(size_t)NN * C];
__device__ float g_s1[NN], g_s2[NN];
__device__ float g_denom[NN * EK];
__device__ float g_workE[(size_t)NE * EK];
__device__ float g_agg[(size_t)NN * EK * C];
__device__ int   g_src[NE], g_dst[NE], g_cnt[NN], g_off[NN + 1], g_pos[NN], g_csr[NE];
__device__ int   g_is64;
__device__ __align__(16) __nv_bfloat16 g_BtWHi[C * C],      g_BtWLo[C * C];
__device__ __align__(16) __nv_bfloat16 g_BtOHi[EK * C * C], g_BtOLo[EK * C * C];

// ---------------- bf16 split GEMM (tensor cores, mma.sync) -------------------
#define MMA_BF16(c, a, b0, b1)                                                 \
    asm volatile(                                                              \
        "mma.sync.aligned.m16n8k16.row.col.f32.bf16.bf16.f32 "                 \
        "{%0,%1,%2,%3}, {%4,%5,%6,%7}, {%8,%9}, {%0,%1,%2,%3};"                \
        : "+f"(c[0]), "+f"(c[1]), "+f"(c[2]), "+f"(c[3])                       \
        : "r"(a[0]), "r"(a[1]), "r"(a[2]), "r"(a[3]), "r"(b0), "r"(b1))

__device__ __forceinline__ uint pack_hi(float x, float y, uint& lo_out) {
    __nv_bfloat16 hx = __float2bfloat16_rn(x);
    __nv_bfloat16 hy = __float2bfloat16_rn(y);
    float lx = x - __bfloat162float(hx);
    float ly = y - __bfloat162float(hy);
    __nv_bfloat16 lxb = __float2bfloat16_rn(lx);
    __nv_bfloat16 lyb = __float2bfloat16_rn(ly);
    lo_out = (uint)__bfloat16_as_ushort(lxb) | ((uint)__bfloat16_as_ushort(lyb) << 16);
    return (uint)__bfloat16_as_ushort(hx) | ((uint)__bfloat16_as_ushort(hy) << 16);
}

// C[M,128] = A[M,KTOT] (f32, split in-kernel) @ Bt[128,KTOT]^T (pre-split bf16)
template <int KTOT>
__global__ __launch_bounds__(256) void bf16gemm(
    const float* __restrict__ A,
    const __nv_bfloat16* __restrict__ BtHi, const __nv_bfloat16* __restrict__ BtLo,
    float* __restrict__ Cm, int M)
{
    extern __shared__ char smem[];
    const int NT = KTOT / 32;

    int tid = threadIdx.x, lane = tid & 31, wid = tid >> 5;
    int gid = lane >> 2, tig = lane & 3;
    int warp_m = wid & 3, warp_n = wid >> 2;
    int row0 = blockIdx.x * 128;

    float acc[2][8][4] = {};
    float4 av[4];
    uint4  bh4[2], bl4[2];

    auto ldg_tile = [&](int t) {
#pragma unroll
        for (int i = 0; i < 4; ++i) {
            int idx = tid + i * 256;
            int r = idx >> 3, c4 = idx & 7;
            int gr = row0 + r;
            av[i] = (gr < M)
                ? reinterpret_cast<const float4*>(A)[(size_t)gr * (KTOT / 4) + t * 8 + c4]
                : make_float4(0.f, 0.f, 0.f, 0.f);
        }
#pragma unroll
        for (int i = 0; i < 2; ++i) {
            int idx = tid + i * 256;
            int n = idx >> 2, c8 = idx & 3;
            size_t base = ((size_t)n * KTOT + (size_t)t * 32) >> 3;
            bh4[i] = reinterpret_cast<const uint4*>(BtHi)[base + c8];
            bl4[i] = reinterpret_cast<const uint4*>(BtLo)[base + c8];
        }
    };
    auto sts_tile = [&](int s) {
        char* st = smem + s * STAGE_BYTES;
#pragma unroll
        for (int i = 0; i < 4; ++i) {
            int idx = tid + i * 256;
            int r = idx >> 3, c4 = idx & 7;
            uint l01, l23;
            uint h01 = pack_hi(av[i].x, av[i].y, l01);
            uint h23 = pack_hi(av[i].z, av[i].w, l23);
            *reinterpret_cast<uint2*>(st + r * RSTRIDE + c4 * 8)         = make_uint2(h01, h23);
            *reinterpret_cast<uint2*>(st + 10240 + r * RSTRIDE + c4 * 8) = make_uint2(l01, l23);
        }
#pragma unroll
        for (int i = 0; i < 2; ++i) {
            int idx = tid + i * 256;
            int n = idx >> 2, c8 = idx & 3;
            *reinterpret_cast<uint4*>(st + 20480 + n * RSTRIDE + c8 * 16) = bh4[i];
            *reinterpret_cast<uint4*>(st + 30720 + n * RSTRIDE + c8 * 16) = bl4[i];
        }
    };

    ldg_tile(0);
    sts_tile(0);
    __syncthreads();

    for (int t = 0; t < NT; ++t) {
        if (t + 1 < NT) ldg_tile(t + 1);
        const char* st = smem + (t & 1) * STAGE_BYTES;
#pragma unroll
        for (int ks = 0; ks < 2; ++ks) {
            int kb = ks * 32;                  // byte offset of k16 step within row
            uint ah[2][4], al[2][4];
#pragma unroll
            for (int mt = 0; mt < 2; ++mt) {
                int r0 = warp_m * 32 + mt * 16 + gid;
                const char* p0 = st + r0 * RSTRIDE + kb + tig * 4;
                ah[mt][0] = *reinterpret_cast<const uint*>(p0);
                ah[mt][1] = *reinterpret_cast<const uint*>(p0 + 8 * RSTRIDE);
                ah[mt][2] = *reinterpret_cast<const uint*>(p0 + 16);
                ah[mt][3] = *reinterpret_cast<const uint*>(p0 + 8 * RSTRIDE + 16);
                const char* p1 = p0 + 10240;
                al[mt][0] = *reinterpret_cast<const uint*>(p1);
                al[mt][1] = *reinterpret_cast<const uint*>(p1 + 8 * RSTRIDE);
                al[mt][2] = *reinterpret_cast<const uint*>(p1 + 16);
                al[mt][3] = *reinterpret_cast<const uint*>(p1 + 8 * RSTRIDE + 16);
            }
#pragma unroll
            for (int nt = 0; nt < 8; ++nt) {
                int n0 = warp_n * 64 + nt * 8 + gid;
                const char* q = st + 20480 + n0 * RSTRIDE + kb + tig * 4;
                uint b0h = *reinterpret_cast<const uint*>(q);
                uint b1h = *reinterpret_cast<const uint*>(q + 16);
                uint b0l = *reinterpret_cast<const uint*>(q + 10240);
                uint b1l = *reinterpret_cast<const uint*>(q + 10240 + 16);
#pragma unroll
                for (int mt = 0; mt < 2; ++mt) {
                    MMA_BF16(acc[mt][nt], ah[mt], b0h, b1h);
                    MMA_BF16(acc[mt][nt], ah[mt], b0l, b1l);
                    MMA_BF16(acc[mt][nt], al[mt], b0h, b1h);
                }
            }
        }
        if (t + 1 < NT) sts_tile((t + 1) & 1);
        __syncthreads();
    }

#pragma unroll
    for (int mt = 0; mt < 2; ++mt)
#pragma unroll
        for (int nt = 0; nt < 8; ++nt) {
            int r1 = row0 + warp_m * 32 + mt * 16 + gid;
            int r2 = r1 + 8;
            int cc = warp_n * 64 + nt * 8 + tig * 2;
            if (r1 < M)
                *reinterpret_cast<float2*>(Cm + (size_t)r1 * C + cc) =
                    make_float2(acc[mt][nt][0], acc[mt][nt][1]);
            if (r2 < M)
                *reinterpret_cast<float2*>(Cm + (size_t)r2 * C + cc) =
                    make_float2(acc[mt][nt][2], acc[mt][nt][3]);
        }
}

// ---------------- prep / edge kernels ----------------------------------------

__global__ void detect_kernel(const int* __restrict__ raw) {
    int t = threadIdx.x;
    int nz = (raw[2 * t + 1] != 0) ? 1 : 0;
    int any = __syncthreads_or(nz);
    if (t == 0) g_is64 = any ? 0 : 1;
}

__global__ void init_kernel() {
    int stride = gridDim.x * blockDim.x;
    int i = blockIdx.x * blockDim.x + threadIdx.x;
    for (int t = i; t < NN * EK; t += stride) g_denom[t] = 0.f;
    for (int t = i; t < NN; t += stride) g_cnt[t] = 0;
}

// unpack indices + count degrees
__global__ void normalize_kernel(const int* __restrict__ raw) {
    int e = blockIdx.x * blockDim.x + threadIdx.x;
    if (e >= NE) return;
    int s, d;
    if (g_is64) { s = raw[2 * e]; d = raw[2 * NE + 2 * e]; }
    else        { s = raw[e];     d = raw[NE + e]; }
    g_src[e] = s;
    g_dst[e] = d;
    atomicAdd(&g_cnt[d], 1);
}

// transpose + bf16-split weights
__global__ void prepB_kernel(const float* __restrict__ W, const float* __restrict__ Wout) {
    int t = blockIdx.x * blockDim.x + threadIdx.x;
    if (t < C * C) {
        int n = t & (C - 1), k = t >> 7;
        float v = W[k * C + n];
        __nv_bfloat16 h = __float2bfloat16_rn(v);
        g_BtWHi[n * C + k] = h;
        g_BtWLo[n * C + k] = __float2bfloat16_rn(v - __bfloat162float(h));
    }
    int t2 = t - C * C;
    if (t2 >= 0 && t2 < EK * C * C) {
        int n = t2 & (C - 1), k = t2 >> 7;
        float v = Wout[k * C + n];
        __nv_bfloat16 h = __float2bfloat16_rn(v);
        g_BtOHi[n * (EK * C) + k] = h;
        g_BtOLo[n * (EK * C) + k] = __float2bfloat16_rn(v - __bfloat162float(h));
    }
}

__global__ __launch_bounds__(SCAN_T) void scan_kernel() {
    __shared__ int s[SCAN_T];
    const int PER = (NN + SCAN_T - 1) / SCAN_T;
    int tid = threadIdx.x;
    int base = tid * PER;
    int sum = 0;
    for (int j = 0; j < PER; j++) {
        int idx = base + j;
        if (idx < NN) sum += g_cnt[idx];
    }
    s[tid] = sum;
    __syncthreads();
    for (int off = 1; off < SCAN_T; off <<= 1) {
        int v = (tid >= off) ? s[tid - off] : 0;
        __syncthreads();
        s[tid] += v;
        __syncthreads();
    }
    int run = s[tid] - sum;
    for (int j = 0; j < PER; j++) {
        int idx = base + j;
        if (idx < NN) {
            g_off[idx] = run;
            g_pos[idx] = run;
            run += g_cnt[idx];
        }
    }
    if (tid == SCAN_T - 1) g_off[NN] = s[SCAN_T - 1];
}

__global__ void scores_kernel(const float* __restrict__ a1, const float* __restrict__ a2) {
    int gw = (blockIdx.x * blockDim.x + threadIdx.x) >> 5;
    int lane = threadIdx.x & 31;
    if (gw >= NN) return;
    float4 w  = reinterpret_cast<const float4*>(g_Wh + (size_t)gw * C)[lane];
    float4 v1 = reinterpret_cast<const float4*>(a1)[lane];
    float4 v2 = reinterpret_cast<const float4*>(a2)[lane];
    float d1 = w.x * v1.x + w.y * v1.y + w.z * v1.z + w.w * v1.w;
    float d2 = w.x * v2.x + w.y * v2.y + w.z * v2.z + w.w * v2.w;
#pragma unroll
    for (int o = 16; o; o >>= 1) {
        d1 += __shfl_xor_sync(0xffffffffu, d1, o);
        d2 += __shfl_xor_sync(0xffffffffu, d2, o);
    }
    if (lane == 0) { g_s1[gw] = d1; g_s2[gw] = d2; }
}

// ex = exp(leakyrelu(s1+s2)*ef); denom += ex; bin edge into CSR (fused)
__global__ void edge_prep_kernel(const float* __restrict__ ef) {
    int e = blockIdx.x * blockDim.x + threadIdx.x;
    if (e >= NE) return;
    int src = g_src[e];
    int dst = g_dst[e];
    float v = g_s1[src] + g_s2[dst];
    v = (v >= 0.f) ? v : LRELU_ALPHA * v;
#pragma unroll
    for (int k = 0; k < EK; k++) {
        float ex = __expf(v * ef[e * EK + k]);
        g_workE[(size_t)e * EK + k] = ex;
        atomicAdd(&g_denom[dst * EK + k], ex);
    }
    int p = atomicAdd(&g_pos[dst], 1);
    g_csr[p] = e;
}

__global__ void aggregate_kernel() {
    int gw = (blockIdx.x * blockDim.x + threadIdx.x) >> 5;
    int lane = threadIdx.x & 31;
    if (gw >= NN) return;
    int beg = g_off[gw], end = g_off[gw + 1];

    float inv0 = 1.f / (g_denom[gw * EK + 0] + 1e-16f);
    float inv1 = 1.f / (g_denom[gw * EK + 1] + 1e-16f);
    float inv2 = 1.f / (g_denom[gw * EK + 2] + 1e-16f);

    float4 acc0 = make_float4(0.f, 0.f, 0.f, 0.f);
    float4 acc1 = acc0, acc2 = acc0;

    for (int t = beg; t < end; ++t) {
        int e   = g_csr[t];
        int src = g_src[e];
        float ex0 = g_workE[(size_t)e * EK + 0];
        float ex1 = g_workE[(size_t)e * EK + 1];
        float ex2 = g_workE[(size_t)e * EK + 2];
        float4 w = reinterpret_cast<const float4*>(g_Wh + (size_t)src * C)[lane];
        acc0.x += w.x * ex0; acc0.y += w.y * ex0; acc0.z += w.z * ex0; acc0.w += w.w * ex0;
        acc1.x += w.x * ex1; acc1.y += w.y * ex1; acc1.z += w.z * ex1; acc1.w += w.w * ex1;
        acc2.x += w.x * ex2; acc2.y += w.y * ex2; acc2.z += w.z * ex2; acc2.w += w.w * ex2;
    }
    acc0.x *= inv0; acc0.y *= inv0; acc0.z *= inv0; acc0.w *= inv0;
    acc1.x *= inv1; acc1.y *= inv1; acc1.z *= inv1; acc1.w *= inv1;
    acc2.x *= inv2; acc2.y *= inv2; acc2.z *= inv2; acc2.w *= inv2;

    float* base = g_agg + (size_t)gw * (EK * C);
    reinterpret_cast<float4*>(base)[lane]         = acc0;
    reinterpret_cast<float4*>(base + C)[lane]     = acc1;
    reinterpret_cast<float4*>(base + 2 * C)[lane] = acc2;
}

// ---------------- launch ------------------------------------------------------

extern "C" void kernel_launch(void* const* d_in, const int* in_sizes, int n_in,
                              void* d_out, int out_size) {
    const float* h    = (const float*)d_in[0];
    const int*   eraw = (const int*)d_in[1];
    const float* ef   = (const float*)d_in[2];
    const float* W    = (const float*)d_in[3];
    const float* a1   = (const float*)d_in[4];
    const float* a2   = (const float*)d_in[5];
    const float* Wout = (const float*)d_in[6];
    float*       out  = (float*)d_out;

    float *pWh, *pAgg;
    __nv_bfloat16 *pWHi, *pWLo, *pOHi, *pOLo;
    cudaGetSymbolAddress((void**)&pWh,  g_Wh);
    cudaGetSymbolAddress((void**)&pAgg, g_agg);
    cudaGetSymbolAddress((void**)&pWHi, g_BtWHi);
    cudaGetSymbolAddress((void**)&pWLo, g_BtWLo);
    cudaGetSymbolAddress((void**)&pOHi, g_BtOHi);
    cudaGetSymbolAddress((void**)&pOLo, g_BtOLo);

    const int MBLK = (NN + 127) / 128;
    const int SMEM = 2 * STAGE_BYTES;   // 81920

    cudaFuncSetAttribute(bf16gemm<128>, cudaFuncAttributeMaxDynamicSharedMemorySize, SMEM);
    cudaFuncSetAttribute(bf16gemm<384>, cudaFuncAttributeMaxDynamicSharedMemorySize, SMEM);

    detect_kernel<<<1, 256>>>(eraw);
    init_kernel<<<512, 256>>>();
    normalize_kernel<<<(NE + 255) / 256, 256>>>(eraw);
    prepB_kernel<<<(C * C + EK * C * C + 255) / 256, 256>>>(W, Wout);
    scan_kernel<<<1, SCAN_T>>>();
    bf16gemm<128><<<MBLK, 256, SMEM>>>(h, pWHi, pWLo, pWh, NN);
    scores_kernel<<<(NN * 32 + 255) / 256, 256>>>(a1, a2);
    edge_prep_kernel<<<(NE + 255) / 256, 256>>>(ef);
    aggregate_kernel<<<(NN * 32 + 255) / 256, 256>>>();
    bf16gemm<384><<<MBLK, 256, SMEM>>>(pAgg, pOHi, pOLo, out, NN);
}

// round 8
// speedup vs baseline: 1.6048x; 1.1736x over previous
#include <cuda_runtime.h>
#include <cuda_bf16.h>
#include <cstdint>

#define NN 50000
#define NE 800000
#define C 128
#define EK 3
#define LRELU_ALPHA 0.2f
#define SCAN_T 1024
#define RSTRIDE 80          // smem row stride in bytes
#define STAGE_BYTES 40960   // Ah(10240) Al(10240) Bh(10240) Bl(10240)

// ---------------- scratch ----------------------------------------------------
__device__ float  g_Wh[(size_t)NN * C];
__device__ float  g_s1[NN], g_s2[NN];
__device__ float4 g_edata[NE];                 // {src_bits, ex0, ex1, ex2} in CSR order
__device__ float  g_agg[(size_t)NN * EK * C];
__device__ int    g_src[NE], g_dst[NE], g_cnt[NN], g_off[NN + 1], g_pos[NN];
__device__ int    g_is64;
__device__ __align__(16) __nv_bfloat16 g_BtWHi[C * C],      g_BtWLo[C * C];
__device__ __align__(16) __nv_bfloat16 g_BtOHi[EK * C * C], g_BtOLo[EK * C * C];

// ---------------- bf16 split GEMM (tensor cores, mma.sync) -------------------
#define MMA_BF16(c, a, b0, b1)                                                 \
    asm volatile(                                                              \
        "mma.sync.aligned.m16n8k16.row.col.f32.bf16.bf16.f32 "                 \
        "{%0,%1,%2,%3}, {%4,%5,%6,%7}, {%8,%9}, {%0,%1,%2,%3};"                \
        : "+f"(c[0]), "+f"(c[1]), "+f"(c[2]), "+f"(c[3])                       \
        : "r"(a[0]), "r"(a[1]), "r"(a[2]), "r"(a[3]), "r"(b0), "r"(b1))

__device__ __forceinline__ uint pack_hi(float x, float y, uint& lo_out) {
    __nv_bfloat16 hx = __float2bfloat16_rn(x);
    __nv_bfloat16 hy = __float2bfloat16_rn(y);
    float lx = x - __bfloat162float(hx);
    float ly = y - __bfloat162float(hy);
    __nv_bfloat16 lxb = __float2bfloat16_rn(lx);
    __nv_bfloat16 lyb = __float2bfloat16_rn(ly);
    lo_out = (uint)__bfloat16_as_ushort(lxb) | ((uint)__bfloat16_as_ushort(lyb) << 16);
    return (uint)__bfloat16_as_ushort(hx) | ((uint)__bfloat16_as_ushort(hy) << 16);
}

// C[M,128] = A[M,KTOT] (f32, split in-kernel) @ Bt[128,KTOT]^T (pre-split bf16)
// SCORES: additionally s1/s2 = Crow . a1 / a2 fused in epilogue.
template <int KTOT, bool SCORES>
__global__ __launch_bounds__(256) void bf16gemm(
    const float* __restrict__ A,
    const __nv_bfloat16* __restrict__ BtHi, const __nv_bfloat16* __restrict__ BtLo,
    float* __restrict__ Cm, int M,
    const float* __restrict__ a1, const float* __restrict__ a2)
{
    extern __shared__ char smem[];
    const int NT = KTOT / 32;

    int tid = threadIdx.x, lane = tid & 31, wid = tid >> 5;
    int gid = lane >> 2, tig = lane & 3;
    int warp_m = wid & 3, warp_n = wid >> 2;
    int row0 = blockIdx.x * 128;

    float acc[2][8][4] = {};
    float4 av[4];
    uint4  bh4[2], bl4[2];

    auto ldg_tile = [&](int t) {
#pragma unroll
        for (int i = 0; i < 4; ++i) {
            int idx = tid + i * 256;
            int r = idx >> 3, c4 = idx & 7;
            int gr = row0 + r;
            av[i] = (gr < M)
                ? reinterpret_cast<const float4*>(A)[(size_t)gr * (KTOT / 4) + t * 8 + c4]
                : make_float4(0.f, 0.f, 0.f, 0.f);
        }
#pragma unroll
        for (int i = 0; i < 2; ++i) {
            int idx = tid + i * 256;
            int n = idx >> 2, c8 = idx & 3;
            size_t base = ((size_t)n * KTOT + (size_t)t * 32) >> 3;
            bh4[i] = reinterpret_cast<const uint4*>(BtHi)[base + c8];
            bl4[i] = reinterpret_cast<const uint4*>(BtLo)[base + c8];
        }
    };
    auto sts_tile = [&](int s) {
        char* st = smem + s * STAGE_BYTES;
#pragma unroll
        for (int i = 0; i < 4; ++i) {
            int idx = tid + i * 256;
            int r = idx >> 3, c4 = idx & 7;
            uint l01, l23;
            uint h01 = pack_hi(av[i].x, av[i].y, l01);
            uint h23 = pack_hi(av[i].z, av[i].w, l23);
            *reinterpret_cast<uint2*>(st + r * RSTRIDE + c4 * 8)         = make_uint2(h01, h23);
            *reinterpret_cast<uint2*>(st + 10240 + r * RSTRIDE + c4 * 8) = make_uint2(l01, l23);
        }
#pragma unroll
        for (int i = 0; i < 2; ++i) {
            int idx = tid + i * 256;
            int n = idx >> 2, c8 = idx & 3;
            *reinterpret_cast<uint4*>(st + 20480 + n * RSTRIDE + c8 * 16) = bh4[i];
            *reinterpret_cast<uint4*>(st + 30720 + n * RSTRIDE + c8 * 16) = bl4[i];
        }
    };

    ldg_tile(0);
    sts_tile(0);
    __syncthreads();

    for (int t = 0; t < NT; ++t) {
        if (t + 1 < NT) ldg_tile(t + 1);
        const char* st = smem + (t & 1) * STAGE_BYTES;
#pragma unroll
        for (int ks = 0; ks < 2; ++ks) {
            int kb = ks * 32;
            uint ah[2][4], al[2][4];
#pragma unroll
            for (int mt = 0; mt < 2; ++mt) {
                int r0 = warp_m * 32 + mt * 16 + gid;
                const char* p0 = st + r0 * RSTRIDE + kb + tig * 4;
                ah[mt][0] = *reinterpret_cast<const uint*>(p0);
                ah[mt][1] = *reinterpret_cast<const uint*>(p0 + 8 * RSTRIDE);
                ah[mt][2] = *reinterpret_cast<const uint*>(p0 + 16);
                ah[mt][3] = *reinterpret_cast<const uint*>(p0 + 8 * RSTRIDE + 16);
                const char* p1 = p0 + 10240;
                al[mt][0] = *reinterpret_cast<const uint*>(p1);
                al[mt][1] = *reinterpret_cast<const uint*>(p1 + 8 * RSTRIDE);
                al[mt][2] = *reinterpret_cast<const uint*>(p1 + 16);
                al[mt][3] = *reinterpret_cast<const uint*>(p1 + 8 * RSTRIDE + 16);
            }
#pragma unroll
            for (int nt = 0; nt < 8; ++nt) {
                int n0 = warp_n * 64 + nt * 8 + gid;
                const char* q = st + 20480 + n0 * RSTRIDE + kb + tig * 4;
                uint b0h = *reinterpret_cast<const uint*>(q);
                uint b1h = *reinterpret_cast<const uint*>(q + 16);
                uint b0l = *reinterpret_cast<const uint*>(q + 10240);
                uint b1l = *reinterpret_cast<const uint*>(q + 10240 + 16);
#pragma unroll
                for (int mt = 0; mt < 2; ++mt) {
                    MMA_BF16(acc[mt][nt], ah[mt], b0h, b1h);
                    MMA_BF16(acc[mt][nt], ah[mt], b0l, b1l);
                    MMA_BF16(acc[mt][nt], al[mt], b0h, b1h);
                }
            }
        }
        if (t + 1 < NT) sts_tile((t + 1) & 1);
        __syncthreads();
    }

    // C store
#pragma unroll
    for (int mt = 0; mt < 2; ++mt)
#pragma unroll
        for (int nt = 0; nt < 8; ++nt) {
            int r1 = row0 + warp_m * 32 + mt * 16 + gid;
            int r2 = r1 + 8;
            int cc = warp_n * 64 + nt * 8 + tig * 2;
            if (r1 < M)
                *reinterpret_cast<float2*>(Cm + (size_t)r1 * C + cc) =
                    make_float2(acc[mt][nt][0], acc[mt][nt][1]);
            if (r2 < M)
                *reinterpret_cast<float2*>(Cm + (size_t)r2 * C + cc) =
                    make_float2(acc[mt][nt][2], acc[mt][nt][3]);
        }

    if (SCORES) {
        // per-thread partial dots of owned row fragments with a1/a2
        float p1[4] = {0.f, 0.f, 0.f, 0.f}, p2[4] = {0.f, 0.f, 0.f, 0.f};
#pragma unroll
        for (int mt = 0; mt < 2; ++mt)
#pragma unroll
            for (int nt = 0; nt < 8; ++nt) {
                int cc = warp_n * 64 + nt * 8 + tig * 2;
                float a1c0 = a1[cc], a1c1 = a1[cc + 1];
                float a2c0 = a2[cc], a2c1 = a2[cc + 1];
                p1[mt * 2 + 0] += acc[mt][nt][0] * a1c0 + acc[mt][nt][1] * a1c1;
                p1[mt * 2 + 1] += acc[mt][nt][2] * a1c0 + acc[mt][nt][3] * a1c1;
                p2[mt * 2 + 0] += acc[mt][nt][0] * a2c0 + acc[mt][nt][1] * a2c1;
                p2[mt * 2 + 1] += acc[mt][nt][2] * a2c0 + acc[mt][nt][3] * a2c1;
            }
#pragma unroll
        for (int o = 1; o <= 2; o <<= 1)
#pragma unroll
            for (int i = 0; i < 4; ++i) {
                p1[i] += __shfl_xor_sync(0xffffffffu, p1[i], o);
                p2[i] += __shfl_xor_sync(0xffffffffu, p2[i], o);
            }
        float* sred = reinterpret_cast<float*>(smem);   // 256 floats
        if (warp_n == 0 && tig == 0) {
#pragma unroll
            for (int i = 0; i < 4; ++i) {
                int r = warp_m * 32 + (i >> 1) * 16 + (i & 1) * 8 + gid;
                sred[r]       = p1[i];
                sred[128 + r] = p2[i];
            }
        }
        __syncthreads();
        if (warp_n == 1 && tig == 0) {
#pragma unroll
            for (int i = 0; i < 4; ++i) {
                int r = warp_m * 32 + (i >> 1) * 16 + (i & 1) * 8 + gid;
                int grow = row0 + r;
                if (grow < NN) {
                    g_s1[grow] = sred[r] + p1[i];
                    g_s2[grow] = sred[128 + r] + p2[i];
                }
            }
        }
    }
}

// ---------------- prep / edge kernels ----------------------------------------

__global__ void detect_kernel(const int* __restrict__ raw) {
    int t = threadIdx.x;
    int nz = (raw[2 * t + 1] != 0) ? 1 : 0;
    int any = __syncthreads_or(nz);
    if (t == 0) g_is64 = any ? 0 : 1;
}

__global__ void init_kernel() {
    int i = blockIdx.x * blockDim.x + threadIdx.x;
    if (i < NN) g_cnt[i] = 0;
}

// unpack indices + count degrees
__global__ void normalize_kernel(const int* __restrict__ raw) {
    int e = blockIdx.x * blockDim.x + threadIdx.x;
    if (e >= NE) return;
    int s, d;
    if (g_is64) { s = raw[2 * e]; d = raw[2 * NE + 2 * e]; }
    else        { s = raw[e];     d = raw[NE + e]; }
    g_src[e] = s;
    g_dst[e] = d;
    atomicAdd(&g_cnt[d], 1);
}

// transpose + bf16-split weights
__global__ void prepB_kernel(const float* __restrict__ W, const float* __restrict__ Wout) {
    int t = blockIdx.x * blockDim.x + threadIdx.x;
    if (t < C * C) {
        int n = t & (C - 1), k = t >> 7;
        float v = W[k * C + n];
        __nv_bfloat16 h = __float2bfloat16_rn(v);
        g_BtWHi[n * C + k] = h;
        g_BtWLo[n * C + k] = __float2bfloat16_rn(v - __bfloat162float(h));
    }
    int t2 = t - C * C;
    if (t2 >= 0 && t2 < EK * C * C) {
        int n = t2 & (C - 1), k = t2 >> 7;
        float v = Wout[k * C + n];
        __nv_bfloat16 h = __float2bfloat16_rn(v);
        g_BtOHi[n * (EK * C) + k] = h;
        g_BtOLo[n * (EK * C) + k] = __float2bfloat16_rn(v - __bfloat162float(h));
    }
}

__global__ __launch_bounds__(SCAN_T) void scan_kernel() {
    __shared__ int s[SCAN_T];
    const int PER = (NN + SCAN_T - 1) / SCAN_T;
    int tid = threadIdx.x;
    int base = tid * PER;
    int sum = 0;
    for (int j = 0; j < PER; j++) {
        int idx = base + j;
        if (idx < NN) sum += g_cnt[idx];
    }
    s[tid] = sum;
    __syncthreads();
    for (int off = 1; off < SCAN_T; off <<= 1) {
        int v = (tid >= off) ? s[tid - off] : 0;
        __syncthreads();
        s[tid] += v;
        __syncthreads();
    }
    int run = s[tid] - sum;
    for (int j = 0; j < PER; j++) {
        int idx = base + j;
        if (idx < NN) {
            g_off[idx] = run;
            g_pos[idx] = run;
            run += g_cnt[idx];
        }
    }
    if (tid == SCAN_T - 1) g_off[NN] = s[SCAN_T - 1];
}

// ex = exp(leakyrelu(s1+s2)*ef); pack {src, ex0..2} into CSR slot (no denom atomics)
__global__ void edge_prep_kernel(const float* __restrict__ ef) {
    int e = blockIdx.x * blockDim.x + threadIdx.x;
    if (e >= NE) return;
    int src = g_src[e];
    int dst = g_dst[e];
    float v = g_s1[src] + g_s2[dst];
    v = (v >= 0.f) ? v : LRELU_ALPHA * v;
    float ex0 = __expf(v * ef[e * EK + 0]);
    float ex1 = __expf(v * ef[e * EK + 1]);
    float ex2 = __expf(v * ef[e * EK + 2]);
    int p = atomicAdd(&g_pos[dst], 1);
    g_edata[p] = make_float4(__int_as_float(src), ex0, ex1, ex2);
}

// gather: one warp per node; batched edge metadata loads + shfl broadcast
__global__ void aggregate_kernel() {
    int gw = (blockIdx.x * blockDim.x + threadIdx.x) >> 5;
    int lane = threadIdx.x & 31;
    if (gw >= NN) return;
    int beg = g_off[gw], end = g_off[gw + 1];

    float den0 = 0.f, den1 = 0.f, den2 = 0.f;
    float4 acc0 = make_float4(0.f, 0.f, 0.f, 0.f);
    float4 acc1 = acc0, acc2 = acc0;

    for (int t0 = beg; t0 < end; t0 += 32) {
        int n = end - t0; if (n > 32) n = 32;
        float4 ed = make_float4(0.f, 0.f, 0.f, 0.f);
        if (lane < n) ed = g_edata[t0 + lane];
#pragma unroll 4
        for (int j = 0; j < n; ++j) {
            int   srcj = __shfl_sync(0xffffffffu, __float_as_int(ed.x), j);
            float e0   = __shfl_sync(0xffffffffu, ed.y, j);
            float e1   = __shfl_sync(0xffffffffu, ed.z, j);
            float e2   = __shfl_sync(0xffffffffu, ed.w, j);
            float4 w = reinterpret_cast<const float4*>(g_Wh + (size_t)srcj * C)[lane];
            den0 += e0; den1 += e1; den2 += e2;
            acc0.x += w.x * e0; acc0.y += w.y * e0; acc0.z += w.z * e0; acc0.w += w.w * e0;
            acc1.x += w.x * e1; acc1.y += w.y * e1; acc1.z += w.z * e1; acc1.w += w.w * e1;
            acc2.x += w.x * e2; acc2.y += w.y * e2; acc2.z += w.z * e2; acc2.w += w.w * e2;
        }
    }
    float inv0 = 1.f / (den0 + 1e-16f);
    float inv1 = 1.f / (den1 + 1e-16f);
    float inv2 = 1.f / (den2 + 1e-16f);
    acc0.x *= inv0; acc0.y *= inv0; acc0.z *= inv0; acc0.w *= inv0;
    acc1.x *= inv1; acc1.y *= inv1; acc1.z *= inv1; acc1.w *= inv1;
    acc2.x *= inv2; acc2.y *= inv2; acc2.z *= inv2; acc2.w *= inv2;

    float* base = g_agg + (size_t)gw * (EK * C);
    reinterpret_cast<float4*>(base)[lane]         = acc0;
    reinterpret_cast<float4*>(base + C)[lane]     = acc1;
    reinterpret_cast<float4*>(base + 2 * C)[lane] = acc2;
}

// ---------------- launch ------------------------------------------------------

extern "C" void kernel_launch(void* const* d_in, const int* in_sizes, int n_in,
                              void* d_out, int out_size) {
    const float* h    = (const float*)d_in[0];
    const int*   eraw = (const int*)d_in[1];
    const float* ef   = (const float*)d_in[2];
    const float* W    = (const float*)d_in[3];
    const float* a1   = (const float*)d_in[4];
    const float* a2   = (const float*)d_in[5];
    const float* Wout = (const float*)d_in[6];
    float*       out  = (float*)d_out;

    float *pWh, *pAgg;
    __nv_bfloat16 *pWHi, *pWLo, *pOHi, *pOLo;
    cudaGetSymbolAddress((void**)&pWh,  g_Wh);
    cudaGetSymbolAddress((void**)&pAgg, g_agg);
    cudaGetSymbolAddress((void**)&pWHi, g_BtWHi);
    cudaGetSymbolAddress((void**)&pWLo, g_BtWLo);
    cudaGetSymbolAddress((void**)&pOHi, g_BtOHi);
    cudaGetSymbolAddress((void**)&pOLo, g_BtOLo);

    const int MBLK = (NN + 127) / 128;
    const int SMEM = 2 * STAGE_BYTES;   // 81920

    cudaFuncSetAttribute((const void*)bf16gemm<128, true>,
                         cudaFuncAttributeMaxDynamicSharedMemorySize, SMEM);
    cudaFuncSetAttribute((const void*)bf16gemm<384, false>,
                         cudaFuncAttributeMaxDynamicSharedMemorySize, SMEM);

    detect_kernel<<<1, 256>>>(eraw);
    init_kernel<<<(NN + 255) / 256, 256>>>();
    normalize_kernel<<<(NE + 255) / 256, 256>>>(eraw);
    prepB_kernel<<<(C * C + EK * C * C + 255) / 256, 256>>>(W, Wout);
    scan_kernel<<<1, SCAN_T>>>();
    bf16gemm<128, true><<<MBLK, 256, SMEM>>>(h, pWHi, pWLo, pWh, NN, a1, a2);
    edge_prep_kernel<<<(NE + 255) / 256, 256>>>(ef);
    aggregate_kernel<<<(NN * 32 + 255) / 256, 256>>>();
    bf16gemm<384, false><<<MBLK, 256, SMEM>>>(pAgg, pOHi, pOLo, out, NN, nullptr, nullptr);
}

// round 9
// speedup vs baseline: 1.6114x; 1.0041x over previous
#include <cuda_runtime.h>
#include <cuda_bf16.h>
#include <cstdint>

#define NN 50000
#define NE 800000
#define C 128
#define EK 3
#define LRELU_ALPHA 0.2f
#define SCAN_T 1024
#define RSTRIDE 80          // smem row stride in bytes
#define STAGE_BYTES 40960   // Ah(10240) Al(10240) Bh(10240) Bl(10240)

// ---------------- scratch ----------------------------------------------------
__device__ float  g_Wh[(size_t)NN * C];
__device__ float  g_s1[NN], g_s2[NN];
__device__ float4 g_edata[NE];                 // {src_bits, ex0, ex1, ex2} CSR order
__device__ float  g_agg[(size_t)NN * EK * C];
__device__ int    g_cnt[NN], g_off[NN + 1], g_pos[NN];
__device__ int    g_is64;
__device__ __align__(16) __nv_bfloat16 g_BtWHi[C * C],      g_BtWLo[C * C];
__device__ __align__(16) __nv_bfloat16 g_BtOHi[EK * C * C], g_BtOLo[EK * C * C];

// ---------------- bf16 split GEMM (tensor cores, mma.sync) -------------------
#define MMA_BF16(c, a, b0, b1)                                                 \
    asm volatile(                                                              \
        "mma.sync.aligned.m16n8k16.row.col.f32.bf16.bf16.f32 "                 \
        "{%0,%1,%2,%3}, {%4,%5,%6,%7}, {%8,%9}, {%0,%1,%2,%3};"                \
        : "+f"(c[0]), "+f"(c[1]), "+f"(c[2]), "+f"(c[3])                       \
        : "r"(a[0]), "r"(a[1]), "r"(a[2]), "r"(a[3]), "r"(b0), "r"(b1))

__device__ __forceinline__ uint pack_hi(float x, float y, uint& lo_out) {
    __nv_bfloat16 hx = __float2bfloat16_rn(x);
    __nv_bfloat16 hy = __float2bfloat16_rn(y);
    float lx = x - __bfloat162float(hx);
    float ly = y - __bfloat162float(hy);
    __nv_bfloat16 lxb = __float2bfloat16_rn(lx);
    __nv_bfloat16 lyb = __float2bfloat16_rn(ly);
    lo_out = (uint)__bfloat16_as_ushort(lxb) | ((uint)__bfloat16_as_ushort(lyb) << 16);
    return (uint)__bfloat16_as_ushort(hx) | ((uint)__bfloat16_as_ushort(hy) << 16);
}

// C[M,128] = A[M,KTOT] (f32, split in-kernel) @ Bt[128,KTOT]^T (pre-split bf16)
template <int KTOT, bool SCORES>
__global__ __launch_bounds__(256) void bf16gemm(
    const float* __restrict__ A,
    const __nv_bfloat16* __restrict__ BtHi, const __nv_bfloat16* __restrict__ BtLo,
    float* __restrict__ Cm, int M,
    const float* __restrict__ a1, const float* __restrict__ a2)
{
    extern __shared__ char smem[];
    const int NT = KTOT / 32;

    int tid = threadIdx.x, lane = tid & 31, wid = tid >> 5;
    int gid = lane >> 2, tig = lane & 3;
    int warp_m = wid & 3, warp_n = wid >> 2;
    int row0 = blockIdx.x * 128;

    float acc[2][8][4] = {};
    float4 av[4];
    uint4  bh4[2], bl4[2];

    auto ldg_tile = [&](int t) {
#pragma unroll
        for (int i = 0; i < 4; ++i) {
            int idx = tid + i * 256;
            int r = idx >> 3, c4 = idx & 7;
            int gr = row0 + r;
            av[i] = (gr < M)
                ? __ldcs(reinterpret_cast<const float4*>(A) + (size_t)gr * (KTOT / 4) + t * 8 + c4)
                : make_float4(0.f, 0.f, 0.f, 0.f);
        }
#pragma unroll
        for (int i = 0; i < 2; ++i) {
            int idx = tid + i * 256;
            int n = idx >> 2, c8 = idx & 3;
            size_t base = ((size_t)n * KTOT + (size_t)t * 32) >> 3;
            bh4[i] = reinterpret_cast<const uint4*>(BtHi)[base + c8];
            bl4[i] = reinterpret_cast<const uint4*>(BtLo)[base + c8];
        }
    };
    auto sts_tile = [&](int s) {
        char* st = smem + s * STAGE_BYTES;
#pragma unroll
        for (int i = 0; i < 4; ++i) {
            int idx = tid + i * 256;
            int r = idx >> 3, c4 = idx & 7;
            uint l01, l23;
            uint h01 = pack_hi(av[i].x, av[i].y, l01);
            uint h23 = pack_hi(av[i].z, av[i].w, l23);
            *reinterpret_cast<uint2*>(st + r * RSTRIDE + c4 * 8)         = make_uint2(h01, h23);
            *reinterpret_cast<uint2*>(st + 10240 + r * RSTRIDE + c4 * 8) = make_uint2(l01, l23);
        }
#pragma unroll
        for (int i = 0; i < 2; ++i) {
            int idx = tid + i * 256;
            int n = idx >> 2, c8 = idx & 3;
            *reinterpret_cast<uint4*>(st + 20480 + n * RSTRIDE + c8 * 16) = bh4[i];
            *reinterpret_cast<uint4*>(st + 30720 + n * RSTRIDE + c8 * 16) = bl4[i];
        }
    };

    ldg_tile(0);
    sts_tile(0);
    __syncthreads();

    for (int t = 0; t < NT; ++t) {
        if (t + 1 < NT) ldg_tile(t + 1);
        const char* st = smem + (t & 1) * STAGE_BYTES;
#pragma unroll
        for (int ks = 0; ks < 2; ++ks) {
            int kb = ks * 32;
            uint ah[2][4], al[2][4];
#pragma unroll
            for (int mt = 0; mt < 2; ++mt) {
                int r0 = warp_m * 32 + mt * 16 + gid;
                const char* p0 = st + r0 * RSTRIDE + kb + tig * 4;
                ah[mt][0] = *reinterpret_cast<const uint*>(p0);
                ah[mt][1] = *reinterpret_cast<const uint*>(p0 + 8 * RSTRIDE);
                ah[mt][2] = *reinterpret_cast<const uint*>(p0 + 16);
                ah[mt][3] = *reinterpret_cast<const uint*>(p0 + 8 * RSTRIDE + 16);
                const char* p1 = p0 + 10240;
                al[mt][0] = *reinterpret_cast<const uint*>(p1);
                al[mt][1] = *reinterpret_cast<const uint*>(p1 + 8 * RSTRIDE);
                al[mt][2] = *reinterpret_cast<const uint*>(p1 + 16);
                al[mt][3] = *reinterpret_cast<const uint*>(p1 + 8 * RSTRIDE + 16);
            }
#pragma unroll
            for (int nt = 0; nt < 8; ++nt) {
                int n0 = warp_n * 64 + nt * 8 + gid;
                const char* q = st + 20480 + n0 * RSTRIDE + kb + tig * 4;
                uint b0h = *reinterpret_cast<const uint*>(q);
                uint b1h = *reinterpret_cast<const uint*>(q + 16);
                uint b0l = *reinterpret_cast<const uint*>(q + 10240);
                uint b1l = *reinterpret_cast<const uint*>(q + 10240 + 16);
#pragma unroll
                for (int mt = 0; mt < 2; ++mt) {
                    MMA_BF16(acc[mt][nt], ah[mt], b0h, b1h);
                    MMA_BF16(acc[mt][nt], ah[mt], b0l, b1l);
                    MMA_BF16(acc[mt][nt], al[mt], b0h, b1h);
                }
            }
        }
        if (t + 1 < NT) sts_tile((t + 1) & 1);
        __syncthreads();
    }

    // C store
#pragma unroll
    for (int mt = 0; mt < 2; ++mt)
#pragma unroll
        for (int nt = 0; nt < 8; ++nt) {
            int r1 = row0 + warp_m * 32 + mt * 16 + gid;
            int r2 = r1 + 8;
            int cc = warp_n * 64 + nt * 8 + tig * 2;
            if (r1 < M)
                *reinterpret_cast<float2*>(Cm + (size_t)r1 * C + cc) =
                    make_float2(acc[mt][nt][0], acc[mt][nt][1]);
            if (r2 < M)
                *reinterpret_cast<float2*>(Cm + (size_t)r2 * C + cc) =
                    make_float2(acc[mt][nt][2], acc[mt][nt][3]);
        }

    if (SCORES) {
        float p1[4] = {0.f, 0.f, 0.f, 0.f}, p2[4] = {0.f, 0.f, 0.f, 0.f};
#pragma unroll
        for (int mt = 0; mt < 2; ++mt)
#pragma unroll
            for (int nt = 0; nt < 8; ++nt) {
                int cc = warp_n * 64 + nt * 8 + tig * 2;
                float a1c0 = a1[cc], a1c1 = a1[cc + 1];
                float a2c0 = a2[cc], a2c1 = a2[cc + 1];
                p1[mt * 2 + 0] += acc[mt][nt][0] * a1c0 + acc[mt][nt][1] * a1c1;
                p1[mt * 2 + 1] += acc[mt][nt][2] * a1c0 + acc[mt][nt][3] * a1c1;
                p2[mt * 2 + 0] += acc[mt][nt][0] * a2c0 + acc[mt][nt][1] * a2c1;
                p2[mt * 2 + 1] += acc[mt][nt][2] * a2c0 + acc[mt][nt][3] * a2c1;
            }
#pragma unroll
        for (int o = 1; o <= 2; o <<= 1)
#pragma unroll
            for (int i = 0; i < 4; ++i) {
                p1[i] += __shfl_xor_sync(0xffffffffu, p1[i], o);
                p2[i] += __shfl_xor_sync(0xffffffffu, p2[i], o);
            }
        float* sred = reinterpret_cast<float*>(smem);
        if (warp_n == 0 && tig == 0) {
#pragma unroll
            for (int i = 0; i < 4; ++i) {
                int r = warp_m * 32 + (i >> 1) * 16 + (i & 1) * 8 + gid;
                sred[r]       = p1[i];
                sred[128 + r] = p2[i];
            }
        }
        __syncthreads();
        if (warp_n == 1 && tig == 0) {
#pragma unroll
            for (int i = 0; i < 4; ++i) {
                int r = warp_m * 32 + (i >> 1) * 16 + (i & 1) * 8 + gid;
                int grow = row0 + r;
                if (grow < NN) {
                    g_s1[grow] = sred[r] + p1[i];
                    g_s2[grow] = sred[128 + r] + p2[i];
                }
            }
        }
    }
}

// ---------------- fused setup: detect dtype + zero cnt + split weights -------
__global__ void setup_kernel(const int* __restrict__ raw,
                             const float* __restrict__ W,
                             const float* __restrict__ Wout) {
    int stride = gridDim.x * blockDim.x;
    int i = blockIdx.x * blockDim.x + threadIdx.x;
    if (blockIdx.x == 0) {
        int nz = (raw[2 * threadIdx.x + 1] != 0) ? 1 : 0;
        int any = __syncthreads_or(nz);
        if (threadIdx.x == 0) g_is64 = any ? 0 : 1;
    }
    for (int t = i; t < NN; t += stride) g_cnt[t] = 0;
    for (int t = i; t < C * C; t += stride) {
        int n = t & (C - 1), k = t >> 7;
        float v = W[k * C + n];
        __nv_bfloat16 h = __float2bfloat16_rn(v);
        g_BtWHi[n * C + k] = h;
        g_BtWLo[n * C + k] = __float2bfloat16_rn(v - __bfloat162float(h));
    }
    for (int t = i; t < EK * C * C; t += stride) {
        int n = t & (C - 1), k = t >> 7;
        float v = Wout[k * C + n];
        __nv_bfloat16 h = __float2bfloat16_rn(v);
        g_BtOHi[n * (EK * C) + k] = h;
        g_BtOLo[n * (EK * C) + k] = __float2bfloat16_rn(v - __bfloat162float(h));
    }
}

// degree count only (reads dst half of raw)
__global__ void normalize_kernel(const int* __restrict__ raw) {
    int e = blockIdx.x * blockDim.x + threadIdx.x;
    if (e >= NE) return;
    int d = g_is64 ? raw[2 * NE + 2 * e] : raw[NE + e];
    atomicAdd(&g_cnt[d], 1);
}

__global__ __launch_bounds__(SCAN_T) void scan_kernel() {
    __shared__ int s[SCAN_T];
    const int PER = (NN + SCAN_T - 1) / SCAN_T;
    int tid = threadIdx.x;
    int base = tid * PER;
    int sum = 0;
    for (int j = 0; j < PER; j++) {
        int idx = base + j;
        if (idx < NN) sum += g_cnt[idx];
    }
    s[tid] = sum;
    __syncthreads();
    for (int off = 1; off < SCAN_T; off <<= 1) {
        int v = (tid >= off) ? s[tid - off] : 0;
        __syncthreads();
        s[tid] += v;
        __syncthreads();
    }
    int run = s[tid] - sum;
    for (int j = 0; j < PER; j++) {
        int idx = base + j;
        if (idx < NN) {
            g_off[idx] = run;
            g_pos[idx] = run;
            run += g_cnt[idx];
        }
    }
    if (tid == SCAN_T - 1) g_off[NN] = s[SCAN_T - 1];
}

// ex = exp(leakyrelu(s1+s2)*ef); pack {src, ex0..2} into CSR slot
__global__ void edge_prep_kernel(const int* __restrict__ raw,
                                 const float* __restrict__ ef) {
    int e = blockIdx.x * blockDim.x + threadIdx.x;
    if (e >= NE) return;
    int src, dst;
    if (g_is64) { src = raw[2 * e]; dst = raw[2 * NE + 2 * e]; }
    else        { src = raw[e];     dst = raw[NE + e]; }
    float v = g_s1[src] + g_s2[dst];
    v = (v >= 0.f) ? v : LRELU_ALPHA * v;
    float ex0 = __expf(v * ef[e * EK + 0]);
    float ex1 = __expf(v * ef[e * EK + 1]);
    float ex2 = __expf(v * ef[e * EK + 2]);
    int p = atomicAdd(&g_pos[dst], 1);
    g_edata[p] = make_float4(__int_as_float(src), ex0, ex1, ex2);
}

// gather: one warp per node; uniform-address edata broadcast loads
__global__ void aggregate_kernel() {
    int gw = (blockIdx.x * blockDim.x + threadIdx.x) >> 5;
    int lane = threadIdx.x & 31;
    if (gw >= NN) return;
    int beg = g_off[gw], end = g_off[gw + 1];

    float den0 = 0.f, den1 = 0.f, den2 = 0.f;
    float4 acc0 = make_float4(0.f, 0.f, 0.f, 0.f);
    float4 acc1 = acc0, acc2 = acc0;

#pragma unroll 4
    for (int t = beg; t < end; ++t) {
        float4 ed = __ldg(&g_edata[t]);            // same addr warp-wide: broadcast
        int   srcj = __float_as_int(ed.x);
        float4 w = __ldg(reinterpret_cast<const float4*>(g_Wh + (size_t)srcj * C) + lane);
        den0 += ed.y; den1 += ed.z; den2 += ed.w;
        acc0.x += w.x * ed.y; acc0.y += w.y * ed.y; acc0.z += w.z * ed.y; acc0.w += w.w * ed.y;
        acc1.x += w.x * ed.z; acc1.y += w.y * ed.z; acc1.z += w.z * ed.z; acc1.w += w.w * ed.z;
        acc2.x += w.x * ed.w; acc2.y += w.y * ed.w; acc2.z += w.z * ed.w; acc2.w += w.w * ed.w;
    }
    float inv0 = 1.f / (den0 + 1e-16f);
    float inv1 = 1.f / (den1 + 1e-16f);
    float inv2 = 1.f / (den2 + 1e-16f);
    acc0.x *= inv0; acc0.y *= inv0; acc0.z *= inv0; acc0.w *= inv0;
    acc1.x *= inv1; acc1.y *= inv1; acc1.z *= inv1; acc1.w *= inv1;
    acc2.x *= inv2; acc2.y *= inv2; acc2.z *= inv2; acc2.w *= inv2;

    float* base = g_agg + (size_t)gw * (EK * C);
    __stwt(reinterpret_cast<float4*>(base) + lane,         acc0);
    __stwt(reinterpret_cast<float4*>(base + C) + lane,     acc1);
    __stwt(reinterpret_cast<float4*>(base + 2 * C) + lane, acc2);
}

// ---------------- launch ------------------------------------------------------

extern "C" void kernel_launch(void* const* d_in, const int* in_sizes, int n_in,
                              void* d_out, int out_size) {
    const float* h    = (const float*)d_in[0];
    const int*   eraw = (const int*)d_in[1];
    const float* ef   = (const float*)d_in[2];
    const float* W    = (const float*)d_in[3];
    const float* a1   = (const float*)d_in[4];
    const float* a2   = (const float*)d_in[5];
    const float* Wout = (const float*)d_in[6];
    float*       out  = (float*)d_out;

    float *pWh, *pAgg;
    __nv_bfloat16 *pWHi, *pWLo, *pOHi, *pOLo;
    cudaGetSymbolAddress((void**)&pWh,  g_Wh);
    cudaGetSymbolAddress((void**)&pAgg, g_agg);
    cudaGetSymbolAddress((void**)&pWHi, g_BtWHi);
    cudaGetSymbolAddress((void**)&pWLo, g_BtWLo);
    cudaGetSymbolAddress((void**)&pOHi, g_BtOHi);
    cudaGetSymbolAddress((void**)&pOLo, g_BtOLo);

    const int MBLK = (NN + 127) / 128;
    const int SMEM = 2 * STAGE_BYTES;   // 81920

    cudaFuncSetAttribute((const void*)bf16gemm<128, true>,
                         cudaFuncAttributeMaxDynamicSharedMemorySize, SMEM);
    cudaFuncSetAttribute((const void*)bf16gemm<384, false>,
                         cudaFuncAttributeMaxDynamicSharedMemorySize, SMEM);

    setup_kernel<<<256, 256>>>(eraw, W, Wout);
    normalize_kernel<<<(NE + 255) / 256, 256>>>(eraw);
    scan_kernel<<<1, SCAN_T>>>();
    bf16gemm<128, true><<<MBLK, 256, SMEM>>>(h, pWHi, pWLo, pWh, NN, a1, a2);
    edge_prep_kernel<<<(NE + 255) / 256, 256>>>(eraw, ef);
    aggregate_kernel<<<(NN * 32 + 255) / 256, 256>>>();
    bf16gemm<384, false><<<MBLK, 256, SMEM>>>(pAgg, pOHi, pOLo, out, NN, nullptr, nullptr);
}

// round 10
// speedup vs baseline: 1.6291x; 1.0110x over previous
#include <cuda_runtime.h>
#include <cuda_bf16.h>
#include <cstdint>

#define NN 50000
#define NE 800000
#define C 128
#define EK 3
#define LRELU_ALPHA 0.2f
#define SCAN_T 1024
#define RSTRIDE 80          // smem row stride in bytes
#define STAGE_BYTES 40960   // Ah(10240) Al(10240) Bh(10240) Bl(10240)

// ---------------- scratch ----------------------------------------------------
__device__ float  g_Wh[(size_t)NN * C];
__device__ float  g_s1[NN], g_s2[NN];
__device__ float4 g_edata[NE];                 // {src_bits, ex0, ex1, ex2} CSR order
__device__ float  g_agg[(size_t)NN * EK * C];
__device__ int    g_cnt[NN], g_off[NN + 1], g_pos[NN];
__device__ int    g_is64;
__device__ __align__(16) __nv_bfloat16 g_BtWHi[C * C],      g_BtWLo[C * C];
__device__ __align__(16) __nv_bfloat16 g_BtOHi[EK * C * C], g_BtOLo[EK * C * C];

// ---------------- bf16 split GEMM (tensor cores, mma.sync) -------------------
#define MMA_BF16(c, a, b0, b1)                                                 \
    asm volatile(                                                              \
        "mma.sync.aligned.m16n8k16.row.col.f32.bf16.bf16.f32 "                 \
        "{%0,%1,%2,%3}, {%4,%5,%6,%7}, {%8,%9}, {%0,%1,%2,%3};"                \
        : "+f"(c[0]), "+f"(c[1]), "+f"(c[2]), "+f"(c[3])                       \
        : "r"(a[0]), "r"(a[1]), "r"(a[2]), "r"(a[3]), "r"(b0), "r"(b1))

__device__ __forceinline__ uint pack_hi(float x, float y, uint& lo_out) {
    __nv_bfloat16 hx = __float2bfloat16_rn(x);
    __nv_bfloat16 hy = __float2bfloat16_rn(y);
    float lx = x - __bfloat162float(hx);
    float ly = y - __bfloat162float(hy);
    __nv_bfloat16 lxb = __float2bfloat16_rn(lx);
    __nv_bfloat16 lyb = __float2bfloat16_rn(ly);
    lo_out = (uint)__bfloat16_as_ushort(lxb) | ((uint)__bfloat16_as_ushort(lyb) << 16);
    return (uint)__bfloat16_as_ushort(hx) | ((uint)__bfloat16_as_ushort(hy) << 16);
}

// C[M,128] = A[M,KTOT] (f32, split in-kernel) @ Bt[128,KTOT]^T (pre-split bf16)
// 512 threads, 16 warps in a 4(M) x 4(N) grid, warp tile 32x32.
template <int KTOT, bool SCORES>
__global__ __launch_bounds__(512) void bf16gemm(
    const float* __restrict__ A,
    const __nv_bfloat16* __restrict__ BtHi, const __nv_bfloat16* __restrict__ BtLo,
    float* __restrict__ Cm, int M,
    const float* __restrict__ a1, const float* __restrict__ a2)
{
    extern __shared__ char smem[];
    const int NT = KTOT / 32;

    int tid = threadIdx.x, lane = tid & 31, wid = tid >> 5;
    int gid = lane >> 2, tig = lane & 3;
    int warp_m = wid & 3, warp_n = wid >> 2;
    int row0 = blockIdx.x * 128;

    float acc[2][4][4] = {};
    float4 av[2];
    uint4  bh4, bl4;

    auto ldg_tile = [&](int t) {
#pragma unroll
        for (int i = 0; i < 2; ++i) {
            int idx = tid + i * 512;
            int r = idx >> 3, c4 = idx & 7;
            int gr = row0 + r;
            av[i] = (gr < M)
                ? __ldcs(reinterpret_cast<const float4*>(A) + (size_t)gr * (KTOT / 4) + t * 8 + c4)
                : make_float4(0.f, 0.f, 0.f, 0.f);
        }
        {
            int n = tid >> 2, c8 = tid & 3;
            size_t base = ((size_t)n * KTOT + (size_t)t * 32) >> 3;
            bh4 = reinterpret_cast<const uint4*>(BtHi)[base + c8];
            bl4 = reinterpret_cast<const uint4*>(BtLo)[base + c8];
        }
    };
    auto sts_tile = [&](int s) {
        char* st = smem + s * STAGE_BYTES;
#pragma unroll
        for (int i = 0; i < 2; ++i) {
            int idx = tid + i * 512;
            int r = idx >> 3, c4 = idx & 7;
            uint l01, l23;
            uint h01 = pack_hi(av[i].x, av[i].y, l01);
            uint h23 = pack_hi(av[i].z, av[i].w, l23);
            *reinterpret_cast<uint2*>(st + r * RSTRIDE + c4 * 8)         = make_uint2(h01, h23);
            *reinterpret_cast<uint2*>(st + 10240 + r * RSTRIDE + c4 * 8) = make_uint2(l01, l23);
        }
        {
            int n = tid >> 2, c8 = tid & 3;
            *reinterpret_cast<uint4*>(st + 20480 + n * RSTRIDE + c8 * 16) = bh4;
            *reinterpret_cast<uint4*>(st + 30720 + n * RSTRIDE + c8 * 16) = bl4;
        }
    };

    ldg_tile(0);
    sts_tile(0);
    __syncthreads();

    for (int t = 0; t < NT; ++t) {
        if (t + 1 < NT) ldg_tile(t + 1);
        const char* st = smem + (t & 1) * STAGE_BYTES;
#pragma unroll
        for (int ks = 0; ks < 2; ++ks) {
            int kb = ks * 32;
            uint ah[2][4], al[2][4];
#pragma unroll
            for (int mt = 0; mt < 2; ++mt) {
                int r0 = warp_m * 32 + mt * 16 + gid;
                const char* p0 = st + r0 * RSTRIDE + kb + tig * 4;
                ah[mt][0] = *reinterpret_cast<const uint*>(p0);
                ah[mt][1] = *reinterpret_cast<const uint*>(p0 + 8 * RSTRIDE);
                ah[mt][2] = *reinterpret_cast<const uint*>(p0 + 16);
                ah[mt][3] = *reinterpret_cast<const uint*>(p0 + 8 * RSTRIDE + 16);
                const char* p1 = p0 + 10240;
                al[mt][0] = *reinterpret_cast<const uint*>(p1);
                al[mt][1] = *reinterpret_cast<const uint*>(p1 + 8 * RSTRIDE);
                al[mt][2] = *reinterpret_cast<const uint*>(p1 + 16);
                al[mt][3] = *reinterpret_cast<const uint*>(p1 + 8 * RSTRIDE + 16);
            }
#pragma unroll
            for (int nt = 0; nt < 4; ++nt) {
                int n0 = warp_n * 32 + nt * 8 + gid;
                const char* q = st + 20480 + n0 * RSTRIDE + kb + tig * 4;
                uint b0h = *reinterpret_cast<const uint*>(q);
                uint b1h = *reinterpret_cast<const uint*>(q + 16);
                uint b0l = *reinterpret_cast<const uint*>(q + 10240);
                uint b1l = *reinterpret_cast<const uint*>(q + 10240 + 16);
#pragma unroll
                for (int mt = 0; mt < 2; ++mt) {
                    MMA_BF16(acc[mt][nt], ah[mt], b0h, b1h);
                    MMA_BF16(acc[mt][nt], ah[mt], b0l, b1l);
                    MMA_BF16(acc[mt][nt], al[mt], b0h, b1h);
                }
            }
        }
        if (t + 1 < NT) sts_tile((t + 1) & 1);
        __syncthreads();
    }

    // C store
#pragma unroll
    for (int mt = 0; mt < 2; ++mt)
#pragma unroll
        for (int nt = 0; nt < 4; ++nt) {
            int r1 = row0 + warp_m * 32 + mt * 16 + gid;
            int r2 = r1 + 8;
            int cc = warp_n * 32 + nt * 8 + tig * 2;
            if (r1 < M)
                *reinterpret_cast<float2*>(Cm + (size_t)r1 * C + cc) =
                    make_float2(acc[mt][nt][0], acc[mt][nt][1]);
            if (r2 < M)
                *reinterpret_cast<float2*>(Cm + (size_t)r2 * C + cc) =
                    make_float2(acc[mt][nt][2], acc[mt][nt][3]);
        }

    if (SCORES) {
        // p[i]: i = mt*2 + j -> row warp_m*32 + mt*16 + j*8 + gid
        float p1[4] = {0.f, 0.f, 0.f, 0.f}, p2[4] = {0.f, 0.f, 0.f, 0.f};
#pragma unroll
        for (int mt = 0; mt < 2; ++mt)
#pragma unroll
            for (int nt = 0; nt < 4; ++nt) {
                int cc = warp_n * 32 + nt * 8 + tig * 2;
                float a1c0 = a1[cc], a1c1 = a1[cc + 1];
                float a2c0 = a2[cc], a2c1 = a2[cc + 1];
                p1[mt * 2 + 0] += acc[mt][nt][0] * a1c0 + acc[mt][nt][1] * a1c1;
                p1[mt * 2 + 1] += acc[mt][nt][2] * a1c0 + acc[mt][nt][3] * a1c1;
                p2[mt * 2 + 0] += acc[mt][nt][0] * a2c0 + acc[mt][nt][1] * a2c1;
                p2[mt * 2 + 1] += acc[mt][nt][2] * a2c0 + acc[mt][nt][3] * a2c1;
            }
#pragma unroll
        for (int o = 1; o <= 2; o <<= 1)
#pragma unroll
            for (int i = 0; i < 4; ++i) {
                p1[i] += __shfl_xor_sync(0xffffffffu, p1[i], o);
                p2[i] += __shfl_xor_sync(0xffffffffu, p2[i], o);
            }
        float* sred = reinterpret_cast<float*>(smem);   // [2][4][128] = 1024 floats
        if (tig == 0) {
#pragma unroll
            for (int i = 0; i < 4; ++i) {
                int r = warp_m * 32 + (i >> 1) * 16 + (i & 1) * 8 + gid;
                sred[warp_n * 128 + r]       = p1[i];
                sred[512 + warp_n * 128 + r] = p2[i];
            }
        }
        __syncthreads();
        if (tid < 128) {
            int grow = row0 + tid;
            if (grow < M) {
                g_s1[grow] = sred[tid] + sred[128 + tid] + sred[256 + tid] + sred[384 + tid];
                g_s2[grow] = sred[512 + tid] + sred[640 + tid] + sred[768 + tid] + sred[896 + tid];
            }
        }
    }
}

// ---------------- fused setup: detect dtype + zero cnt + split weights -------
__global__ void setup_kernel(const int* __restrict__ raw,
                             const float* __restrict__ W,
                             const float* __restrict__ Wout) {
    int stride = gridDim.x * blockDim.x;
    int i = blockIdx.x * blockDim.x + threadIdx.x;
    if (blockIdx.x == 0) {
        int nz = (raw[2 * threadIdx.x + 1] != 0) ? 1 : 0;
        int any = __syncthreads_or(nz);
        if (threadIdx.x == 0) g_is64 = any ? 0 : 1;
    }
    for (int t = i; t < NN; t += stride) g_cnt[t] = 0;
    for (int t = i; t < C * C; t += stride) {
        int n = t & (C - 1), k = t >> 7;
        float v = W[k * C + n];
        __nv_bfloat16 h = __float2bfloat16_rn(v);
        g_BtWHi[n * C + k] = h;
        g_BtWLo[n * C + k] = __float2bfloat16_rn(v - __bfloat162float(h));
    }
    for (int t = i; t < EK * C * C; t += stride) {
        int n = t & (C - 1), k = t >> 7;
        float v = Wout[k * C + n];
        __nv_bfloat16 h = __float2bfloat16_rn(v);
        g_BtOHi[n * (EK * C) + k] = h;
        g_BtOLo[n * (EK * C) + k] = __float2bfloat16_rn(v - __bfloat162float(h));
    }
}

// degree count only (reads dst half of raw)
__global__ void normalize_kernel(const int* __restrict__ raw) {
    int e = blockIdx.x * blockDim.x + threadIdx.x;
    if (e >= NE) return;
    int d = g_is64 ? raw[2 * NE + 2 * e] : raw[NE + e];
    atomicAdd(&g_cnt[d], 1);
}

__global__ __launch_bounds__(SCAN_T) void scan_kernel() {
    __shared__ int s[SCAN_T];
    const int PER = (NN + SCAN_T - 1) / SCAN_T;
    int tid = threadIdx.x;
    int base = tid * PER;
    int sum = 0;
    for (int j = 0; j < PER; j++) {
        int idx = base + j;
        if (idx < NN) sum += g_cnt[idx];
    }
    s[tid] = sum;
    __syncthreads();
    for (int off = 1; off < SCAN_T; off <<= 1) {
        int v = (tid >= off) ? s[tid - off] : 0;
        __syncthreads();
        s[tid] += v;
        __syncthreads();
    }
    int run = s[tid] - sum;
    for (int j = 0; j < PER; j++) {
        int idx = base + j;
        if (idx < NN) {
            g_off[idx] = run;
            g_pos[idx] = run;
            run += g_cnt[idx];
        }
    }
    if (tid == SCAN_T - 1) g_off[NN] = s[SCAN_T - 1];
}

// ex = exp(leakyrelu(s1+s2)*ef); pack {src, ex0..2} into CSR slot
__global__ void edge_prep_kernel(const int* __restrict__ raw,
                                 const float* __restrict__ ef) {
    int e = blockIdx.x * blockDim.x + threadIdx.x;
    if (e >= NE) return;
    int src, dst;
    if (g_is64) { src = raw[2 * e]; dst = raw[2 * NE + 2 * e]; }
    else        { src = raw[e];     dst = raw[NE + e]; }
    float v = g_s1[src] + g_s2[dst];
    v = (v >= 0.f) ? v : LRELU_ALPHA * v;
    float ex0 = __expf(v * ef[e * EK + 0]);
    float ex1 = __expf(v * ef[e * EK + 1]);
    float ex2 = __expf(v * ef[e * EK + 2]);
    int p = atomicAdd(&g_pos[dst], 1);
    g_edata[p] = make_float4(__int_as_float(src), ex0, ex1, ex2);
}

// gather: one warp per node; uniform-address edata broadcast loads
__global__ void aggregate_kernel() {
    int gw = (blockIdx.x * blockDim.x + threadIdx.x) >> 5;
    int lane = threadIdx.x & 31;
    if (gw >= NN) return;
    int beg = g_off[gw], end = g_off[gw + 1];

    float den0 = 0.f, den1 = 0.f, den2 = 0.f;
    float4 acc0 = make_float4(0.f, 0.f, 0.f, 0.f);
    float4 acc1 = acc0, acc2 = acc0;

#pragma unroll 4
    for (int t = beg; t < end; ++t) {
        float4 ed = __ldg(&g_edata[t]);            // same addr warp-wide: broadcast
        int   srcj = __float_as_int(ed.x);
        float4 w = __ldg(reinterpret_cast<const float4*>(g_Wh + (size_t)srcj * C) + lane);
        den0 += ed.y; den1 += ed.z; den2 += ed.w;
        acc0.x += w.x * ed.y; acc0.y += w.y * ed.y; acc0.z += w.z * ed.y; acc0.w += w.w * ed.y;
        acc1.x += w.x * ed.z; acc1.y += w.y * ed.z; acc1.z += w.z * ed.z; acc1.w += w.w * ed.z;
        acc2.x += w.x * ed.w; acc2.y += w.y * ed.w; acc2.z += w.z * ed.w; acc2.w += w.w * ed.w;
    }
    float inv0 = 1.f / (den0 + 1e-16f);
    float inv1 = 1.f / (den1 + 1e-16f);
    float inv2 = 1.f / (den2 + 1e-16f);
    acc0.x *= inv0; acc0.y *= inv0; acc0.z *= inv0; acc0.w *= inv0;
    acc1.x *= inv1; acc1.y *= inv1; acc1.z *= inv1; acc1.w *= inv1;
    acc2.x *= inv2; acc2.y *= inv2; acc2.z *= inv2; acc2.w *= inv2;

    float* base = g_agg + (size_t)gw * (EK * C);
    __stwt(reinterpret_cast<float4*>(base) + lane,         acc0);
    __stwt(reinterpret_cast<float4*>(base + C) + lane,     acc1);
    __stwt(reinterpret_cast<float4*>(base + 2 * C) + lane, acc2);
}

// ---------------- launch ------------------------------------------------------

extern "C" void kernel_launch(void* const* d_in, const int* in_sizes, int n_in,
                              void* d_out, int out_size) {
    const float* h    = (const float*)d_in[0];
    const int*   eraw = (const int*)d_in[1];
    const float* ef   = (const float*)d_in[2];
    const float* W    = (const float*)d_in[3];
    const float* a1   = (const float*)d_in[4];
    const float* a2   = (const float*)d_in[5];
    const float* Wout = (const float*)d_in[6];
    float*       out  = (float*)d_out;

    float *pWh, *pAgg;
    __nv_bfloat16 *pWHi, *pWLo, *pOHi, *pOLo;
    cudaGetSymbolAddress((void**)&pWh,  g_Wh);
    cudaGetSymbolAddress((void**)&pAgg, g_agg);
    cudaGetSymbolAddress((void**)&pWHi, g_BtWHi);
    cudaGetSymbolAddress((void**)&pWLo, g_BtWLo);
    cudaGetSymbolAddress((void**)&pOHi, g_BtOHi);
    cudaGetSymbolAddress((void**)&pOLo, g_BtOLo);

    const int MBLK = (NN + 127) / 128;
    const int SMEM = 2 * STAGE_BYTES;   // 81920

    cudaFuncSetAttribute((const void*)bf16gemm<128, true>,
                         cudaFuncAttributeMaxDynamicSharedMemorySize, SMEM);
    cudaFuncSetAttribute((const void*)bf16gemm<384, false>,
                         cudaFuncAttributeMaxDynamicSharedMemorySize, SMEM);

    setup_kernel<<<256, 256>>>(eraw, W, Wout);
    normalize_kernel<<<(NE + 255) / 256, 256>>>(eraw);
    scan_kernel<<<1, SCAN_T>>>();
    bf16gemm<128, true><<<MBLK, 512, SMEM>>>(h, pWHi, pWLo, pWh, NN, a1, a2);
    edge_prep_kernel<<<(NE + 255) / 256, 256>>>(eraw, ef);
    aggregate_kernel<<<(NN * 32 + 255) / 256, 256>>>();
    bf16gemm<384, false><<<MBLK, 512, SMEM>>>(pAgg, pOHi, pOLo, out, NN, nullptr, nullptr);
}